// round 15
// baseline (speedup 1.0000x reference)
#include <cuda_runtime.h>
#include <math.h>

#define BB 32
#define DD 1024
#define TXX 4096
#define WIN 4
#define NW 8
#define KC 64
#define GRID 320
#define BLOCK 256

// Scratch (device globals; allocation forbidden). All split-K partials in
// private slabs, reduced in fixed order -> deterministic.
__device__ float g_t_part[16][BB][DD];     // input @ W_in^T partials
__device__ float g_pt_part[16][BB][512];   // input @ W_p1^T partials
__device__ float g_h_part[32][BB][DD];     // cat @ W_out^T partials
__device__ float g_weighted[BB * DD];      // attn-weighted context
__device__ float g_hU[BB * DD];            // reduced upper (input) half of h

// Dataflow counters (monotonic; reset at kernel end -> identical each replay)
__device__ volatile unsigned cA, cB, cC, cW, cG, cU;
__device__ unsigned cDone;

__device__ __forceinline__ void ctr_inc(volatile unsigned* c) {
    __syncthreads();
    __threadfence();
    if (threadIdx.x == 0) atomicAdd((unsigned*)c, 1u);
}
__device__ __forceinline__ void ctr_wait(volatile unsigned* c, unsigned tgt) {
    if (threadIdx.x == 0) { while (*c < tgt) __nanosleep(32); }
    __syncthreads();
    __threadfence();
}
__device__ __forceinline__ void ctr_wait2(volatile unsigned* a, unsigned ta,
                                          volatile unsigned* b, unsigned tb) {
    if (threadIdx.x == 0) { while (*a < ta || *b < tb) __nanosleep(32); }
    __syncthreads();
    __threadfence();
}

// ---------------------------------------------------------------------------
// Tile: out[32, j0:+128] = X[:, kx0:+64] * W[j, kw0:+64]^T  (256 threads)
// smem layout: Xs[64][36] at sm, Ws[64][132] at sm+2304 (43008B total)
__device__ __forceinline__ void loadW128(float* sm, const float* __restrict__ W,
                                         int wstride, int kw0, int j0)
{
    float (*Ws)[132] = (float (*)[132])(sm + 64 * 36);
    const int t = threadIdx.x;
    const float4* W4 = (const float4*)W;
#pragma unroll
    for (int i = t; i < 128 * 16; i += BLOCK) {
        int j = i >> 4, kq = i & 15;
        float4 v = W4[(size_t)(j0 + j) * (wstride >> 2) + (kw0 >> 2) + kq];
        Ws[kq * 4 + 0][j] = v.x; Ws[kq * 4 + 1][j] = v.y;
        Ws[kq * 4 + 2][j] = v.z; Ws[kq * 4 + 3][j] = v.w;
    }
}

__device__ __forceinline__ void loadX(float* sm, const float* __restrict__ X,
                                      int xstride, int kx0)
{
    float (*Xs)[36] = (float (*)[36])sm;
    const int t = threadIdx.x;
    const float4* X4 = (const float4*)X;
#pragma unroll
    for (int i = t; i < 32 * 16; i += BLOCK) {
        int b = i >> 4, kq = i & 15;
        float4 v = X4[(size_t)b * (xstride >> 2) + (kx0 >> 2) + kq];
        Xs[kq * 4 + 0][b] = v.x; Xs[kq * 4 + 1][b] = v.y;
        Xs[kq * 4 + 2][b] = v.z; Xs[kq * 4 + 3][b] = v.w;
    }
}

__device__ void compute128(float* sm, float* __restrict__ out, int ostride, int j0)
{
    float (*Xs)[36]  = (float (*)[36])sm;
    float (*Ws)[132] = (float (*)[132])(sm + 64 * 36);
    const int t  = threadIdx.x;
    const int tb = t & 7;
    const int tj = t >> 3;

    float acc[4][4];
#pragma unroll
    for (int i = 0; i < 4; i++)
#pragma unroll
        for (int j = 0; j < 4; j++) acc[i][j] = 0.f;

#pragma unroll 32
    for (int k = 0; k < KC; k++) {
        float4 x = *(const float4*)&Xs[k][tb * 4];
        float4 w = *(const float4*)&Ws[k][tj * 4];
        acc[0][0] += x.x * w.x; acc[0][1] += x.x * w.y; acc[0][2] += x.x * w.z; acc[0][3] += x.x * w.w;
        acc[1][0] += x.y * w.x; acc[1][1] += x.y * w.y; acc[1][2] += x.y * w.z; acc[1][3] += x.y * w.w;
        acc[2][0] += x.z * w.x; acc[2][1] += x.z * w.y; acc[2][2] += x.z * w.z; acc[2][3] += x.z * w.w;
        acc[3][0] += x.w * w.x; acc[3][1] += x.w * w.y; acc[3][2] += x.w * w.z; acc[3][3] += x.w * w.w;
    }

#pragma unroll
    for (int i = 0; i < 4; i++) {
        float4 v = make_float4(acc[i][0], acc[i][1], acc[i][2], acc[i][3]);
        *(float4*)&out[(size_t)(tb * 4 + i) * ostride + j0 + tj * 4] = v;
    }
}

__device__ void gemm_j128(float* sm,
                          const float* __restrict__ X, int xstride, int kx0,
                          const float* __restrict__ W, int wstride, int kw0,
                          float* __restrict__ out, int ostride, int j0)
{
    __syncthreads();                 // previous smem user done
    loadX(sm, X, xstride, kx0);
    loadW128(sm, W, wstride, kw0, j0);
    __syncthreads();
    compute128(sm, out, ostride, j0);
}

// ---------------------------------------------------------------------------
__global__ void __launch_bounds__(BLOCK, 4)
k_all(const float* __restrict__ input,
      const float* __restrict__ context,
      const float* __restrict__ W_in,
      const float* __restrict__ W_p1,
      const float* __restrict__ W_p2,
      const float* __restrict__ W_out,
      float* __restrict__ out) {
    __shared__ __align__(16) float s_raw[10752];  // 43008B
    __shared__ float s_red[4], s_part[NW], s_attn[NW];
    __shared__ int   s_idx[NW];

    const int r = blockIdx.x;
    const int t = threadIdx.x;
    const int warp = t >> 5, lane = t & 31;

    // ==== Stage 1: one input-dependent GEMM tile per block ====
    if (r < 128) {                       // A: W_in (8jt x 16kt)
        int jt = r & 7, kt = r >> 3;
        gemm_j128(s_raw, input, DD, kt * KC, W_in, DD, kt * KC,
                  &g_t_part[kt][0][0], DD, jt * 128);
        ctr_inc(&cA);
    } else if (r < 192) {                // B: W_p1 (4jt x 16kt)
        int bi = r - 128, jt = bi & 3, kt = bi >> 2;
        gemm_j128(s_raw, input, DD, kt * KC, W_p1, DD, kt * KC,
                  &g_pt_part[kt][0][0], 512, jt * 128);
        ctr_inc(&cB);
    } else {                             // C: W_out upper half (8jt x 16kt)
        int ci = r - 192, jt = ci & 7, kt = ci >> 3;
        gemm_j128(s_raw, input, DD, kt * KC, W_out, 2 * DD, DD + kt * KC,
                  &g_h_part[16 + kt][0][0], DD, jt * 128);
        ctr_inc(&cC);
    }

    // ==== Stage 2 ====
    if (r < BB) {
        // ---- attention, one block per batch ----
        const int b = r;
        float (*s_cw)[DD] = (float (*)[DD])s_raw;   // 8 x 1024
        float* s_t = s_raw + NW * DD;               // 1024

        // pt score needs only B partials
        ctr_wait(&cB, 64);
        if (t < 128) {
            float4 v = make_float4(0.f, 0.f, 0.f, 0.f);
#pragma unroll
            for (int p = 0; p < 16; p++) {
                float4 u = ((const float4*)&g_pt_part[p][b][0])[t];
                v.x += u.x; v.y += u.y; v.z += u.z; v.w += u.w;
            }
            float4 w = ((const float4*)W_p2)[t];
            float local = tanhf(v.x) * w.x + tanhf(v.y) * w.y
                        + tanhf(v.z) * w.z + tanhf(v.w) * w.w;
#pragma unroll
            for (int o = 16; o; o >>= 1) local += __shfl_xor_sync(0xffffffffu, local, o);
            if (lane == 0) s_red[warp] = local;
        }
        __syncthreads();

        if (t == 0) {
            float s = s_red[0] + s_red[1] + s_red[2] + s_red[3];
            float pt2 = (float)TXX * (1.f / (1.f + expf(-s)));
            int bl = (int)truncf(pt2 - (float)WIN);   // jnp.trunc -> int32
#pragma unroll
            for (int w = 0; w < NW; w++) {
                int id = bl + w;
                id = id < 0 ? 0 : (id > TXX - 1 ? TXX - 1 : id);
                s_idx[w] = id;
            }
        }
        __syncthreads();

        // gather (DRAM-cold) issued BEFORE waiting on A tiles
        {
            const float4* crow =
                (const float4*)&context[((size_t)b * TXX + s_idx[warp]) * DD];
            float4* dst = (float4*)&s_cw[warp][0];
#pragma unroll
            for (int i = lane; i < 256; i += 32) dst[i] = crow[i];
        }

        // target row = fixed-order reduce of 16 partials (needs all A tiles)
        ctr_wait(&cA, 128);
        {
            float4 v = make_float4(0.f, 0.f, 0.f, 0.f);
#pragma unroll
            for (int p = 0; p < 16; p++) {
                float4 u = ((const float4*)&g_t_part[p][b][0])[t];
                v.x += u.x; v.y += u.y; v.z += u.z; v.w += u.w;
            }
            ((float4*)s_t)[t] = v;
        }
        __syncthreads();

        // scores: one warp per row
        {
            const float4* c4 = (const float4*)&s_cw[warp][0];
            const float4* t4 = (const float4*)s_t;
            float p = 0.f;
#pragma unroll
            for (int i = lane; i < 256; i += 32) {
                float4 c = c4[i], x = t4[i];
                p += c.x * x.x + c.y * x.y + c.z * x.z + c.w * x.w;
            }
#pragma unroll
            for (int o = 16; o; o >>= 1) p += __shfl_xor_sync(0xffffffffu, p, o);
            if (lane == 0) s_part[warp] = p;
        }
        __syncthreads();

        // softmax over 8 (+ attn output)
        if (t == 0) {
            float m = -1e30f;
#pragma unroll
            for (int w = 0; w < NW; w++) m = fmaxf(m, s_part[w]);
            float e[NW], sum = 0.f;
#pragma unroll
            for (int w = 0; w < NW; w++) { e[w] = expf(s_part[w] - m); sum += e[w]; }
            float inv = 1.f / sum;
#pragma unroll
            for (int w = 0; w < NW; w++) {
                float a = e[w] * inv;
                s_attn[w] = a;
                out[BB * DD + b * NW + w] = a;
            }
        }
        __syncthreads();

        // weighted[b,:] = sum_w attn[w] * cw[w,:]
        {
            float4 acc = make_float4(0.f, 0.f, 0.f, 0.f);
#pragma unroll
            for (int w = 0; w < NW; w++) {
                float a = s_attn[w];
                float4 c = ((const float4*)&s_cw[w][0])[t];
                acc.x += a * c.x; acc.y += a * c.y; acc.z += a * c.z; acc.w += a * c.w;
            }
            ((float4*)&g_weighted[b * DD])[t] = acc;
        }
        ctr_inc(&cW);
    } else if (r < 160) {
        // ---- G: weighted-half W_out tiles (8jt x 16kt) on blocks 32..159 ----
        // Prefetch W tile into smem BEFORE the dependency wait (runs during attn)
        int gi = r - 32, jt = gi & 7, kt = gi >> 3;
        __syncthreads();   // stage-1 smem reads done
        loadW128(s_raw, W_out, 2 * DD, kt * KC, jt * 128);
        ctr_wait(&cW, BB);
        loadX(s_raw, g_weighted, DD, kt * KC);
        __syncthreads();
        compute128(s_raw, &g_h_part[kt][0][0], DD, jt * 128);
        ctr_inc(&cG);
    } else if (r >= 192) {
        // ---- upper-half h reduce on blocks 192..319 ----
        ctr_wait(&cC, 128);
        int i = (r - 192) * BLOCK + t;   // [0, 32768)
        float v = 0.f;
#pragma unroll
        for (int p = 16; p < 32; p++) v += g_h_part[p][0][i];
        g_hU[i] = v;
        ctr_inc(&cU);
    }
    // blocks 160..191: done after their B tile

    // ==== Stage 3: final reduce + tanh on blocks 0..127 ====
    if (r < 128) {
        ctr_wait2(&cG, 128, &cU, 128);
        int i = r * BLOCK + t;           // [0, 32768)
        float v = g_hU[i];
#pragma unroll
        for (int p = 0; p < 16; p++) v += g_h_part[p][0][i];
        out[i] = tanhf(v);
    }

    // ==== Reset counters for next (identical) replay ====
    __syncthreads();
    if (t == 0) {
        unsigned d = atomicAdd(&cDone, 1u) + 1u;
        if (d == GRID) {
            *(unsigned*)&cA = 0u; *(unsigned*)&cB = 0u; *(unsigned*)&cC = 0u;
            *(unsigned*)&cW = 0u; *(unsigned*)&cG = 0u; *(unsigned*)&cU = 0u;
            cDone = 0u;
            __threadfence();
        }
    }
}

// ---------------------------------------------------------------------------
extern "C" void kernel_launch(void* const* d_in, const int* in_sizes, int n_in,
                              void* d_out, int out_size) {
    const float *input = 0, *context = 0, *W_in = 0, *W_out = 0, *W_p1 = 0, *W_p2 = 0;
    for (int i = 0; i < n_in; i++) {
        switch (in_sizes[i]) {
            case BB * DD:       input   = (const float*)d_in[i]; break;
            case BB * TXX * DD: context = (const float*)d_in[i]; break;
            case DD * DD:       W_in    = (const float*)d_in[i]; break;
            case DD * 2 * DD:   W_out   = (const float*)d_in[i]; break;
            case 512 * DD:      W_p1    = (const float*)d_in[i]; break;
            case 512:           W_p2    = (const float*)d_in[i]; break;
        }
    }
    k_all<<<GRID, BLOCK>>>(input, context, W_in, W_p1, W_p2, W_out, (float*)d_out);
}

// round 16
// speedup vs baseline: 1.0760x; 1.0760x over previous
#include <cuda_runtime.h>
#include <math.h>

#define BB 32
#define DD 1024
#define TXX 4096
#define WIN 4
#define NW 8
#define KC 64
#define GRID 296          // exactly 2 blocks per SM (148 SMs)
#define BLOCK 256

// Scratch (device globals; allocation forbidden). All split-K partials in
// private slabs, reduced in fixed order -> deterministic.
__device__ float g_t_part[16][BB][DD];     // input @ W_in^T partials
__device__ float g_pt_part[16][BB][512];   // input @ W_p1^T partials
__device__ float g_h_part[32][BB][DD];     // cat @ W_out^T partials
__device__ float g_weighted[BB * DD];      // attn-weighted context
__device__ float g_hU[BB * DD];            // reduced upper (input) half of h

// Dataflow counters (monotonic; reset at kernel end -> identical each replay)
__device__ volatile unsigned cA, cB, cC, cW, cG, cU;
__device__ unsigned cDone;

__device__ __forceinline__ void ctr_inc(volatile unsigned* c) {
    __syncthreads();
    __threadfence();
    if (threadIdx.x == 0) atomicAdd((unsigned*)c, 1u);
}
__device__ __forceinline__ void ctr_wait(volatile unsigned* c, unsigned tgt) {
    if (threadIdx.x == 0) { while (*c < tgt) __nanosleep(32); }
    __syncthreads();
    __threadfence();
}
__device__ __forceinline__ void ctr_wait2(volatile unsigned* a, unsigned ta,
                                          volatile unsigned* b, unsigned tb) {
    if (threadIdx.x == 0) { while (*a < ta || *b < tb) __nanosleep(32); }
    __syncthreads();
    __threadfence();
}

// ---------------------------------------------------------------------------
// Tile: out[32, j0:+128] = X[:, kx0:+64] * W[j, kw0:+64]^T  (256 threads)
// smem layout: Xs[64][36] at sm, Ws[64][132] at sm+2304 (43008B total)
__device__ __forceinline__ void loadW128(float* sm, const float* __restrict__ W,
                                         int wstride, int kw0, int j0)
{
    float (*Ws)[132] = (float (*)[132])(sm + 64 * 36);
    const int t = threadIdx.x;
    const float4* W4 = (const float4*)W;
#pragma unroll
    for (int i = t; i < 128 * 16; i += BLOCK) {
        int j = i >> 4, kq = i & 15;
        float4 v = W4[(size_t)(j0 + j) * (wstride >> 2) + (kw0 >> 2) + kq];
        Ws[kq * 4 + 0][j] = v.x; Ws[kq * 4 + 1][j] = v.y;
        Ws[kq * 4 + 2][j] = v.z; Ws[kq * 4 + 3][j] = v.w;
    }
}

__device__ __forceinline__ void loadX(float* sm, const float* __restrict__ X,
                                      int xstride, int kx0)
{
    float (*Xs)[36] = (float (*)[36])sm;
    const int t = threadIdx.x;
    const float4* X4 = (const float4*)X;
#pragma unroll
    for (int i = t; i < 32 * 16; i += BLOCK) {
        int b = i >> 4, kq = i & 15;
        float4 v = X4[(size_t)b * (xstride >> 2) + (kx0 >> 2) + kq];
        Xs[kq * 4 + 0][b] = v.x; Xs[kq * 4 + 1][b] = v.y;
        Xs[kq * 4 + 2][b] = v.z; Xs[kq * 4 + 3][b] = v.w;
    }
}

__device__ void compute128(float* sm, float* __restrict__ out, int ostride, int j0)
{
    float (*Xs)[36]  = (float (*)[36])sm;
    float (*Ws)[132] = (float (*)[132])(sm + 64 * 36);
    const int t  = threadIdx.x;
    const int tb = t & 7;
    const int tj = t >> 3;

    float acc[4][4];
#pragma unroll
    for (int i = 0; i < 4; i++)
#pragma unroll
        for (int j = 0; j < 4; j++) acc[i][j] = 0.f;

#pragma unroll 16
    for (int k = 0; k < KC; k++) {
        float4 x = *(const float4*)&Xs[k][tb * 4];
        float4 w = *(const float4*)&Ws[k][tj * 4];
        acc[0][0] += x.x * w.x; acc[0][1] += x.x * w.y; acc[0][2] += x.x * w.z; acc[0][3] += x.x * w.w;
        acc[1][0] += x.y * w.x; acc[1][1] += x.y * w.y; acc[1][2] += x.y * w.z; acc[1][3] += x.y * w.w;
        acc[2][0] += x.z * w.x; acc[2][1] += x.z * w.y; acc[2][2] += x.z * w.z; acc[2][3] += x.z * w.w;
        acc[3][0] += x.w * w.x; acc[3][1] += x.w * w.y; acc[3][2] += x.w * w.z; acc[3][3] += x.w * w.w;
    }

#pragma unroll
    for (int i = 0; i < 4; i++) {
        float4 v = make_float4(acc[i][0], acc[i][1], acc[i][2], acc[i][3]);
        *(float4*)&out[(size_t)(tb * 4 + i) * ostride + j0 + tj * 4] = v;
    }
}

__device__ void gemm_j128(float* sm,
                          const float* __restrict__ X, int xstride, int kx0,
                          const float* __restrict__ W, int wstride, int kw0,
                          float* __restrict__ out, int ostride, int j0)
{
    __syncthreads();                 // previous smem user done
    loadX(sm, X, xstride, kx0);
    loadW128(sm, W, wstride, kw0, j0);
    __syncthreads();
    compute128(sm, out, ostride, j0);
}

// ---------------------------------------------------------------------------
__global__ void __launch_bounds__(BLOCK, 3)
k_all(const float* __restrict__ input,
      const float* __restrict__ context,
      const float* __restrict__ W_in,
      const float* __restrict__ W_p1,
      const float* __restrict__ W_p2,
      const float* __restrict__ W_out,
      float* __restrict__ out) {
    __shared__ __align__(16) float s_raw[10752];  // 43008B
    __shared__ float s_red[4], s_part[NW], s_attn[NW];
    __shared__ int   s_idx[NW];

    const int r = blockIdx.x;
    const int t = threadIdx.x;
    const int warp = t >> 5, lane = t & 31;

    // ==== Stage 1: input-dependent GEMM tiles ====
    // A: blocks 0..127 (one tile), B: 128..191 (one tile),
    // C: blocks 192..295 — 128 tiles; blocks 192..215 take a second tile.
    if (r < 128) {                       // A: W_in (8jt x 16kt)
        int jt = r & 7, kt = r >> 3;
        gemm_j128(s_raw, input, DD, kt * KC, W_in, DD, kt * KC,
                  &g_t_part[kt][0][0], DD, jt * 128);
        ctr_inc(&cA);
    } else if (r < 192) {                // B: W_p1 (4jt x 16kt)
        int bi = r - 128, jt = bi & 3, kt = bi >> 2;
        gemm_j128(s_raw, input, DD, kt * KC, W_p1, DD, kt * KC,
                  &g_pt_part[kt][0][0], 512, jt * 128);
        ctr_inc(&cB);
    } else {                             // C: W_out upper half (8jt x 16kt)
        int ci = r - 192;                // first C tile: 0..103
        {
            int jt = ci & 7, kt = ci >> 3;
            gemm_j128(s_raw, input, DD, kt * KC, W_out, 2 * DD, DD + kt * KC,
                      &g_h_part[16 + kt][0][0], DD, jt * 128);
            ctr_inc(&cC);
        }
        if (ci < 24) {                   // second C tile: 104..127
            int c2 = ci + 104, jt = c2 & 7, kt = c2 >> 3;
            gemm_j128(s_raw, input, DD, kt * KC, W_out, 2 * DD, DD + kt * KC,
                      &g_h_part[16 + kt][0][0], DD, jt * 128);
            ctr_inc(&cC);
        }
    }

    // ==== Stage 2 ====
    if (r < BB) {
        // ---- attention, one block per batch ----
        const int b = r;
        float (*s_cw)[DD] = (float (*)[DD])s_raw;   // 8 x 1024
        float* s_t = s_raw + NW * DD;               // 1024

        // pt score needs only B partials
        ctr_wait(&cB, 64);
        if (t < 128) {
            float4 v = make_float4(0.f, 0.f, 0.f, 0.f);
#pragma unroll
            for (int p = 0; p < 16; p++) {
                float4 u = ((const float4*)&g_pt_part[p][b][0])[t];
                v.x += u.x; v.y += u.y; v.z += u.z; v.w += u.w;
            }
            float4 w = ((const float4*)W_p2)[t];
            float local = tanhf(v.x) * w.x + tanhf(v.y) * w.y
                        + tanhf(v.z) * w.z + tanhf(v.w) * w.w;
#pragma unroll
            for (int o = 16; o; o >>= 1) local += __shfl_xor_sync(0xffffffffu, local, o);
            if (lane == 0) s_red[warp] = local;
        }
        __syncthreads();

        if (t == 0) {
            float s = s_red[0] + s_red[1] + s_red[2] + s_red[3];
            float pt2 = (float)TXX * (1.f / (1.f + expf(-s)));
            int bl = (int)truncf(pt2 - (float)WIN);   // jnp.trunc -> int32
#pragma unroll
            for (int w = 0; w < NW; w++) {
                int id = bl + w;
                id = id < 0 ? 0 : (id > TXX - 1 ? TXX - 1 : id);
                s_idx[w] = id;
            }
        }
        __syncthreads();

        // gather (DRAM-cold) issued BEFORE waiting on A tiles
        {
            const float4* crow =
                (const float4*)&context[((size_t)b * TXX + s_idx[warp]) * DD];
            float4* dst = (float4*)&s_cw[warp][0];
#pragma unroll
            for (int i = lane; i < 256; i += 32) dst[i] = crow[i];
        }

        // target row = fixed-order reduce of 16 partials (needs all A tiles)
        ctr_wait(&cA, 128);
        {
            float4 v = make_float4(0.f, 0.f, 0.f, 0.f);
#pragma unroll
            for (int p = 0; p < 16; p++) {
                float4 u = ((const float4*)&g_t_part[p][b][0])[t];
                v.x += u.x; v.y += u.y; v.z += u.z; v.w += u.w;
            }
            ((float4*)s_t)[t] = v;
        }
        __syncthreads();

        // scores: one warp per row
        {
            const float4* c4 = (const float4*)&s_cw[warp][0];
            const float4* t4 = (const float4*)s_t;
            float p = 0.f;
#pragma unroll
            for (int i = lane; i < 256; i += 32) {
                float4 c = c4[i], x = t4[i];
                p += c.x * x.x + c.y * x.y + c.z * x.z + c.w * x.w;
            }
#pragma unroll
            for (int o = 16; o; o >>= 1) p += __shfl_xor_sync(0xffffffffu, p, o);
            if (lane == 0) s_part[warp] = p;
        }
        __syncthreads();

        // softmax over 8 (+ attn output)
        if (t == 0) {
            float m = -1e30f;
#pragma unroll
            for (int w = 0; w < NW; w++) m = fmaxf(m, s_part[w]);
            float e[NW], sum = 0.f;
#pragma unroll
            for (int w = 0; w < NW; w++) { e[w] = expf(s_part[w] - m); sum += e[w]; }
            float inv = 1.f / sum;
#pragma unroll
            for (int w = 0; w < NW; w++) {
                float a = e[w] * inv;
                s_attn[w] = a;
                out[BB * DD + b * NW + w] = a;
            }
        }
        __syncthreads();

        // weighted[b,:] = sum_w attn[w] * cw[w,:]
        {
            float4 acc = make_float4(0.f, 0.f, 0.f, 0.f);
#pragma unroll
            for (int w = 0; w < NW; w++) {
                float a = s_attn[w];
                float4 c = ((const float4*)&s_cw[w][0])[t];
                acc.x += a * c.x; acc.y += a * c.y; acc.z += a * c.z; acc.w += a * c.w;
            }
            ((float4*)&g_weighted[b * DD])[t] = acc;
        }
        ctr_inc(&cW);
    } else if (r < 160) {
        // ---- G: weighted-half W_out tiles (8jt x 16kt) on blocks 32..159 ----
        // Prefetch W tile into smem BEFORE the dependency wait (runs during attn)
        int gi = r - 32, jt = gi & 7, kt = gi >> 3;
        __syncthreads();   // stage-1 smem reads done
        loadW128(s_raw, W_out, 2 * DD, kt * KC, jt * 128);
        ctr_wait(&cW, BB);
        loadX(s_raw, g_weighted, DD, kt * KC);
        __syncthreads();
        compute128(s_raw, &g_h_part[kt][0][0], DD, jt * 128);
        ctr_inc(&cG);
    } else if (r >= 192) {
        // ---- upper-half h reduce on blocks 192..295 (128 segments) ----
        ctr_wait(&cC, 128);
        int seg = r - 192;                   // 0..103
        {
            int i = seg * BLOCK + t;         // [0, 32768)
            float v = 0.f;
#pragma unroll
            for (int p = 16; p < 32; p++) v += g_h_part[p][0][i];
            g_hU[i] = v;
            ctr_inc(&cU);
        }
        if (seg < 24) {                      // second segment: 104..127
            int i = (seg + 104) * BLOCK + t;
            float v = 0.f;
#pragma unroll
            for (int p = 16; p < 32; p++) v += g_h_part[p][0][i];
            g_hU[i] = v;
            ctr_inc(&cU);
        }
    }
    // blocks 160..191: done after their B tile

    // ==== Stage 3: final reduce + tanh on blocks 0..127 ====
    if (r < 128) {
        ctr_wait2(&cG, 128, &cU, 128);
        int i = r * BLOCK + t;           // [0, 32768)
        float v = g_hU[i];
#pragma unroll
        for (int p = 0; p < 16; p++) v += g_h_part[p][0][i];
        out[i] = tanhf(v);
    }

    // ==== Reset counters for next (identical) replay ====
    __syncthreads();
    if (t == 0) {
        unsigned d = atomicAdd(&cDone, 1u) + 1u;
        if (d == GRID) {
            *(unsigned*)&cA = 0u; *(unsigned*)&cB = 0u; *(unsigned*)&cC = 0u;
            *(unsigned*)&cW = 0u; *(unsigned*)&cG = 0u; *(unsigned*)&cU = 0u;
            cDone = 0u;
            __threadfence();
        }
    }
}

// ---------------------------------------------------------------------------
extern "C" void kernel_launch(void* const* d_in, const int* in_sizes, int n_in,
                              void* d_out, int out_size) {
    const float *input = 0, *context = 0, *W_in = 0, *W_out = 0, *W_p1 = 0, *W_p2 = 0;
    for (int i = 0; i < n_in; i++) {
        switch (in_sizes[i]) {
            case BB * DD:       input   = (const float*)d_in[i]; break;
            case BB * TXX * DD: context = (const float*)d_in[i]; break;
            case DD * DD:       W_in    = (const float*)d_in[i]; break;
            case DD * 2 * DD:   W_out   = (const float*)d_in[i]; break;
            case 512 * DD:      W_p1    = (const float*)d_in[i]; break;
            case 512:           W_p2    = (const float*)d_in[i]; break;
        }
    }
    k_all<<<GRID, BLOCK>>>(input, context, W_in, W_p1, W_p2, W_out, (float*)d_out);
}